// round 3
// baseline (speedup 1.0000x reference)
#include <cuda_runtime.h>

// ---------------------------------------------------------------------------
// Problem constants (match reference)
// ---------------------------------------------------------------------------
#define NP   500000
#define NB   20000
#define NCA  5000
#define NSH  2000
#define NTOT 527000          // NP+NB+NCA+NSH
#define EE   500000          // edges per relation (one direction)
#define H    64
#define ODIM 32
#define FIN  384

// ---------------------------------------------------------------------------
// Scratch (device globals: allocation-free rule)
// ---------------------------------------------------------------------------
__device__ float g_x0[(size_t)NTOT * H];    // layer-0 features
__device__ float g_h1[(size_t)NTOT * H];    // layer-1 output
__device__ float g_agg[(size_t)NTOT * H];   // aggregation buffer (reused)
__device__ float g_deg[NTOT];               // degree -> 1/max(deg,1)

// ---------------------------------------------------------------------------
// f32x2 packed-FMA helpers (Blackwell: FFMA2 doubles FP32 throughput)
// ---------------------------------------------------------------------------
__device__ __forceinline__ unsigned long long ffma2(unsigned long long a,
                                                    unsigned long long b,
                                                    unsigned long long c) {
    unsigned long long d;
    asm("fma.rn.f32x2 %0, %1, %2, %3;" : "=l"(d) : "l"(a), "l"(b), "l"(c));
    return d;
}
__device__ __forceinline__ unsigned long long bcast2(float v) {
    unsigned long long r;
    unsigned int u = __float_as_uint(v);
    asm("mov.b64 %0, {%1, %2};" : "=l"(r) : "r"(u), "r"(u));
    return r;
}
__device__ __forceinline__ float2 unpack2(unsigned long long v) {
    unsigned int lo, hi;
    asm("mov.b64 {%0, %1}, %2;" : "=r"(lo), "=r"(hi) : "l"(v));
    return make_float2(__uint_as_float(lo), __uint_as_float(hi));
}

// ---------------------------------------------------------------------------
// Zero agg (+ optionally deg)
// ---------------------------------------------------------------------------
__global__ void zero_kernel(int also_deg) {
    int i = blockIdx.x * 256 + threadIdx.x;
    const int n4 = NTOT * H / 4;
    if (i < n4)
        reinterpret_cast<float4*>(g_agg)[i] = make_float4(0.f, 0.f, 0.f, 0.f);
    if (also_deg && i < NTOT) g_deg[i] = 0.f;
}

// ---------------------------------------------------------------------------
// Degree count / inverse
// ---------------------------------------------------------------------------
__global__ void deg_kernel(const int* __restrict__ idx, int off) {
    int i = blockIdx.x * 256 + threadIdx.x;
    if (i < EE) atomicAdd(&g_deg[idx[i] + off], 1.0f);
}
__global__ void inv_kernel() {
    int i = blockIdx.x * 256 + threadIdx.x;
    if (i < NTOT) g_deg[i] = 1.0f / fmaxf(g_deg[i], 1.0f);
}

// ---------------------------------------------------------------------------
// Copy embeddings into g_x0 rows [NP, NTOT)
// ---------------------------------------------------------------------------
__global__ void copy_emb_kernel(const float* __restrict__ eb,
                                const float* __restrict__ ec,
                                const float* __restrict__ es) {
    int i = blockIdx.x * 256 + threadIdx.x;
    const int nb4 = NB * H / 4, nc4 = NCA * H / 4, ns4 = NSH * H / 4;
    float4* dst = reinterpret_cast<float4*>(g_x0 + (size_t)NP * H);
    if (i < nb4)
        dst[i] = reinterpret_cast<const float4*>(eb)[i];
    else if (i < nb4 + nc4)
        dst[i] = reinterpret_cast<const float4*>(ec)[i - nb4];
    else if (i < nb4 + nc4 + ns4)
        dst[i] = reinterpret_cast<const float4*>(es)[i - nb4 - nc4];
}

// ---------------------------------------------------------------------------
// Projection: g_x0[0:NP] = relu(x_product @ W_proj^T + b_proj)
// 256 threads, 128 rows x 64 cols per block. Full W^T (384x64, 96KB) staged
// in shared once per block; X staged in 16-wide k-tiles.
// Thread: 4 rows (interleaved rg+32*i) x 8 cols (cg*8), f32x2 accumulators.
// ---------------------------------------------------------------------------
#define PROJ_BR 128
#define PROJ_KT 16
#define PROJ_XS 20   // Xs row stride (pad: rows land on distinct banks)
#define PROJ_SMEM ((FIN * 64 + PROJ_BR * PROJ_XS) * 4)

__global__ void proj_kernel(const float* __restrict__ X,
                            const float* __restrict__ W,
                            const float* __restrict__ b) {
    extern __shared__ float sm[];
    float* WT = sm;                 // [384][64] k-major
    float* Xs = sm + FIN * 64;      // [128][PROJ_XS]
    const int t = threadIdx.x;

    for (int e = t; e < FIN * 64; e += 256) {
        int c = e & 63, k = e >> 6;
        WT[k * 64 + c] = W[c * FIN + k];
    }

    const int row0 = blockIdx.x * PROJ_BR;
    const int cg = t & 7;    // 8 col-groups of 8 cols
    const int rg = t >> 3;   // 32 row-groups; rows rg + 32*i

    unsigned long long acc[4][4];
#pragma unroll
    for (int i = 0; i < 4; i++)
#pragma unroll
        for (int j = 0; j < 4; j++) acc[i][j] = 0ull;

    for (int kt = 0; kt < FIN; kt += PROJ_KT) {
        __syncthreads();
        for (int e = t; e < PROJ_BR * 4; e += 256) {
            int r = e >> 2, q = (e & 3) * 4;
            int grow = row0 + r;
            if (grow >= NP) grow = NP - 1;
            *(float4*)&Xs[r * PROJ_XS + q] =
                *(const float4*)&X[(size_t)grow * FIN + kt + q];
        }
        __syncthreads();
#pragma unroll
        for (int kk = 0; kk < PROJ_KT; kk++) {
            const int k = kt + kk;
            const ulonglong2 w0 = *(const ulonglong2*)&WT[k * 64 + cg * 8];
            const ulonglong2 w1 = *(const ulonglong2*)&WT[k * 64 + cg * 8 + 4];
#pragma unroll
            for (int i = 0; i < 4; i++) {
                unsigned long long xv = bcast2(Xs[(rg + 32 * i) * PROJ_XS + kk]);
                acc[i][0] = ffma2(xv, w0.x, acc[i][0]);
                acc[i][1] = ffma2(xv, w0.y, acc[i][1]);
                acc[i][2] = ffma2(xv, w1.x, acc[i][2]);
                acc[i][3] = ffma2(xv, w1.y, acc[i][3]);
            }
        }
    }

    float bias[8];
#pragma unroll
    for (int j = 0; j < 8; j++) bias[j] = b[cg * 8 + j];
#pragma unroll
    for (int i = 0; i < 4; i++) {
        int grow = row0 + rg + 32 * i;
        if (grow < NP) {
            float o[8];
#pragma unroll
            for (int j = 0; j < 4; j++) {
                float2 p = unpack2(acc[i][j]);
                o[2 * j]     = fmaxf(p.x + bias[2 * j], 0.f);
                o[2 * j + 1] = fmaxf(p.y + bias[2 * j + 1], 0.f);
            }
            float* dst = &g_x0[(size_t)grow * H + cg * 8];
            *(float4*)dst       = make_float4(o[0], o[1], o[2], o[3]);
            *(float4*)(dst + 4) = make_float4(o[4], o[5], o[6], o[7]);
        }
    }
}

// ---------------------------------------------------------------------------
// Edge scatter: agg[dst] += x[src]  (64 floats/edge, 16 threads/edge)
// ---------------------------------------------------------------------------
__global__ void scatter_kernel(const int* __restrict__ src, int soff,
                               const int* __restrict__ dst, int doff,
                               const float* __restrict__ x) {
    int tid = blockIdx.x * 256 + threadIdx.x;
    int e = tid >> 4;
    if (e >= EE) return;
    int c = (tid & 15) * 4;
    int s = src[e] + soff;
    int d = dst[e] + doff;
    float4 v = *(const float4*)&x[(size_t)s * H + c];
    float* a = &g_agg[(size_t)d * H + c];
    atomicAdd(a + 0, v.x);
    atomicAdd(a + 1, v.y);
    atomicAdd(a + 2, v.z);
    atomicAdd(a + 3, v.w);
}

// ---------------------------------------------------------------------------
// SAGE combine: out = [relu]( (agg*inv) @ Wl^T + bl + x @ Wr^T )
// 256 threads, 128 rows per block, OUT cols. K = 64 fully staged.
// Thread: R rows (interleaved) x 8 cols, f32x2 accumulators.
// ---------------------------------------------------------------------------
template <int OUT, bool RELU>
__global__ void combine_kernel(const float* __restrict__ agg,
                               const float* __restrict__ x,
                               const float* __restrict__ Wl,
                               const float* __restrict__ bl,
                               const float* __restrict__ Wr,
                               float* __restrict__ out) {
    constexpr int BR = 128;
    constexpr int COLG = OUT / 8;       // col-groups (8 cols each)
    constexpr int RG = 256 / COLG;      // row-groups
    constexpr int R = BR / RG;          // rows per thread
    constexpr int STR = 68;             // padded row stride

    extern __shared__ float sm[];
    float* WlT = sm;                    // [64][OUT] k-major
    float* WrT = WlT + 64 * OUT;
    float* As  = WrT + 64 * OUT;        // [BR][STR]
    float* Xs  = As + BR * STR;

    const int t = threadIdx.x;
    for (int e = t; e < 64 * OUT; e += 256) {
        int c = e % OUT, k = e / OUT;
        WlT[k * OUT + c] = Wl[c * 64 + k];
        WrT[k * OUT + c] = Wr[c * 64 + k];
    }

    const int row0 = blockIdx.x * BR;
    for (int e = t; e < BR * 16; e += 256) {
        int r = e >> 4, q = (e & 15) * 4;
        int grow = row0 + r;
        if (grow >= NTOT) grow = NTOT - 1;
        float iv = g_deg[grow];
        float4 av = *(const float4*)&agg[(size_t)grow * H + q];
        av.x *= iv; av.y *= iv; av.z *= iv; av.w *= iv;
        *(float4*)&As[r * STR + q] = av;
        *(float4*)&Xs[r * STR + q] = *(const float4*)&x[(size_t)grow * H + q];
    }
    __syncthreads();

    const int cg = t % COLG;
    const int rg = t / COLG;

    unsigned long long acc[R][4];
#pragma unroll
    for (int i = 0; i < R; i++)
#pragma unroll
        for (int j = 0; j < 4; j++) acc[i][j] = 0ull;

#pragma unroll 2
    for (int k = 0; k < 64; k++) {
        const ulonglong2 wl0 = *(const ulonglong2*)&WlT[k * OUT + cg * 8];
        const ulonglong2 wl1 = *(const ulonglong2*)&WlT[k * OUT + cg * 8 + 4];
        const ulonglong2 wr0 = *(const ulonglong2*)&WrT[k * OUT + cg * 8];
        const ulonglong2 wr1 = *(const ulonglong2*)&WrT[k * OUT + cg * 8 + 4];
#pragma unroll
        for (int i = 0; i < R; i++) {
            const int r = rg + RG * i;
            unsigned long long a2 = bcast2(As[r * STR + k]);
            unsigned long long x2 = bcast2(Xs[r * STR + k]);
            acc[i][0] = ffma2(a2, wl0.x, acc[i][0]);
            acc[i][0] = ffma2(x2, wr0.x, acc[i][0]);
            acc[i][1] = ffma2(a2, wl0.y, acc[i][1]);
            acc[i][1] = ffma2(x2, wr0.y, acc[i][1]);
            acc[i][2] = ffma2(a2, wl1.x, acc[i][2]);
            acc[i][2] = ffma2(x2, wr1.x, acc[i][2]);
            acc[i][3] = ffma2(a2, wl1.y, acc[i][3]);
            acc[i][3] = ffma2(x2, wr1.y, acc[i][3]);
        }
    }

    float bias[8];
#pragma unroll
    for (int j = 0; j < 8; j++) bias[j] = bl[cg * 8 + j];
#pragma unroll
    for (int i = 0; i < R; i++) {
        int grow = row0 + rg + RG * i;
        if (grow < NTOT) {
            float o[8];
#pragma unroll
            for (int j = 0; j < 4; j++) {
                float2 p = unpack2(acc[i][j]);
                float v0 = p.x + bias[2 * j];
                float v1 = p.y + bias[2 * j + 1];
                if (RELU) { v0 = fmaxf(v0, 0.f); v1 = fmaxf(v1, 0.f); }
                o[2 * j] = v0; o[2 * j + 1] = v1;
            }
            float* dst = &out[(size_t)grow * OUT + cg * 8];
            *(float4*)dst       = make_float4(o[0], o[1], o[2], o[3]);
            *(float4*)(dst + 4) = make_float4(o[4], o[5], o[6], o[7]);
        }
    }
}

// ---------------------------------------------------------------------------
// Host launch sequence (graph-capturable, allocation-free)
// ---------------------------------------------------------------------------
extern "C" void kernel_launch(void* const* d_in, const int* in_sizes, int n_in,
                              void* d_out, int out_size) {
    (void)in_sizes; (void)n_in; (void)out_size;

    const float* x_product = (const float*)d_in[0];
    const int*   pb_src    = (const int*)d_in[1];
    const int*   pb_dst    = (const int*)d_in[2];
    const int*   pc_src    = (const int*)d_in[3];
    const int*   pc_dst    = (const int*)d_in[4];
    const int*   ps_src    = (const int*)d_in[5];
    const int*   ps_dst    = (const int*)d_in[6];
    const float* W_proj    = (const float*)d_in[7];
    const float* b_proj    = (const float*)d_in[8];
    const float* emb_b     = (const float*)d_in[9];
    const float* emb_c     = (const float*)d_in[10];
    const float* emb_s     = (const float*)d_in[11];
    const float* W1l       = (const float*)d_in[12];
    const float* b1l       = (const float*)d_in[13];
    const float* W1r       = (const float*)d_in[14];
    const float* W2l       = (const float*)d_in[15];
    const float* b2l       = (const float*)d_in[16];
    const float* W2r       = (const float*)d_in[17];
    float* out = (float*)d_out;

    float *px0, *ph1, *pagg;
    cudaGetSymbolAddress((void**)&px0, g_x0);
    cudaGetSymbolAddress((void**)&ph1, g_h1);
    cudaGetSymbolAddress((void**)&pagg, g_agg);

    const int CMB64_SMEM = (64 * 64 * 2 + 128 * 68 * 2) * 4;   // 102400
    const int CMB32_SMEM = (64 * 32 * 2 + 128 * 68 * 2) * 4;   //  86016
    cudaFuncSetAttribute(proj_kernel,
                         cudaFuncAttributeMaxDynamicSharedMemorySize, PROJ_SMEM);
    cudaFuncSetAttribute(combine_kernel<64, true>,
                         cudaFuncAttributeMaxDynamicSharedMemorySize, CMB64_SMEM);
    cudaFuncSetAttribute(combine_kernel<32, false>,
                         cudaFuncAttributeMaxDynamicSharedMemorySize, CMB32_SMEM);

    const int ZB   = (NTOT * H / 4 + 255) / 256;
    const int DB   = (EE + 255) / 256;
    const int IB   = (NTOT + 255) / 256;
    const int CPB  = ((NB + NCA + NSH) * H / 4 + 255) / 256;
    const int PRB  = (NP + PROJ_BR - 1) / PROJ_BR;
    const int SCB  = (EE * 16 + 255) / 256;
    const int CMB  = (NTOT + 127) / 128;

    const int b_off = NP;
    const int c_off = NP + NB;
    const int s_off = NP + NB + NCA;

    // 1. zero agg + deg
    zero_kernel<<<ZB, 256>>>(1);

    // 2. degree counts over all 6 directed lists (shared by both layers)
    deg_kernel<<<DB, 256>>>(pb_dst, b_off);
    deg_kernel<<<DB, 256>>>(pb_src, 0);
    deg_kernel<<<DB, 256>>>(pc_dst, c_off);
    deg_kernel<<<DB, 256>>>(pc_src, 0);
    deg_kernel<<<DB, 256>>>(ps_dst, s_off);
    deg_kernel<<<DB, 256>>>(ps_src, 0);
    inv_kernel<<<IB, 256>>>();

    // 3. node features: projection + embedding copy
    proj_kernel<<<PRB, 256, PROJ_SMEM>>>(x_product, W_proj, b_proj);
    copy_emb_kernel<<<CPB, 256>>>(emb_b, emb_c, emb_s);

    // 4. layer-1 aggregation
    scatter_kernel<<<SCB, 256>>>(pb_src, 0, pb_dst, b_off, px0);
    scatter_kernel<<<SCB, 256>>>(pb_dst, b_off, pb_src, 0, px0);
    scatter_kernel<<<SCB, 256>>>(pc_src, 0, pc_dst, c_off, px0);
    scatter_kernel<<<SCB, 256>>>(pc_dst, c_off, pc_src, 0, px0);
    scatter_kernel<<<SCB, 256>>>(ps_src, 0, ps_dst, s_off, px0);
    scatter_kernel<<<SCB, 256>>>(ps_dst, s_off, ps_src, 0, px0);

    // 5. layer-1 combine (relu)
    combine_kernel<64, true><<<CMB, 256, CMB64_SMEM>>>(pagg, px0, W1l, b1l, W1r, ph1);

    // 6. layer-2 aggregation (re-zero agg)
    zero_kernel<<<ZB, 256>>>(0);
    scatter_kernel<<<SCB, 256>>>(pb_src, 0, pb_dst, b_off, ph1);
    scatter_kernel<<<SCB, 256>>>(pb_dst, b_off, pb_src, 0, ph1);
    scatter_kernel<<<SCB, 256>>>(pc_src, 0, pc_dst, c_off, ph1);
    scatter_kernel<<<SCB, 256>>>(pc_dst, c_off, pc_src, 0, ph1);
    scatter_kernel<<<SCB, 256>>>(ps_src, 0, ps_dst, s_off, ph1);
    scatter_kernel<<<SCB, 256>>>(ps_dst, s_off, ps_src, 0, ph1);

    // 7. layer-2 combine -> d_out [N, 32]
    combine_kernel<32, false><<<CMB, 256, CMB32_SMEM>>>(pagg, ph1, W2l, b2l, W2r, out);
}

// round 4
// speedup vs baseline: 1.2372x; 1.2372x over previous
#include <cuda_runtime.h>

// ---------------------------------------------------------------------------
// Problem constants (match reference)
// ---------------------------------------------------------------------------
#define NP   500000
#define NB   20000
#define NCA  5000
#define NSH  2000
#define NTOT 527000          // NP+NB+NCA+NSH
#define EE   500000          // edges per relation (one direction)
#define E6   (6 * EE)        // total directed edges
#define H    64
#define ODIM 32
#define FIN  384

#define BOFF NP
#define COFF (NP + NB)
#define SOFF (NP + NB + NCA)

#define SCAN_NB ((NTOT + 1023) / 1024)   // 515

// ---------------------------------------------------------------------------
// Scratch (device globals: allocation-free rule)
// ---------------------------------------------------------------------------
__device__ float g_x0[(size_t)NTOT * H];    // layer-0 features
__device__ float g_h1[(size_t)NTOT * H];    // layer-1 output
__device__ float g_agg[(size_t)NTOT * H];   // aggregation buffer (reused)
__device__ float g_deg[NTOT];               // 1/max(in-degree,1)
__device__ int   g_cnt[NTOT];               // in-degree counts
__device__ int   g_row[NTOT + 1];           // CSR row starts
__device__ int   g_fill[NTOT];              // fill cursors
__device__ int   g_eidx[E6];                // CSR src indices (dst-sorted)
__device__ int   g_bsum[SCAN_NB];           // scan block sums

// ---------------------------------------------------------------------------
// f32x2 packed-FMA helpers (Blackwell: FFMA2 doubles FP32 throughput)
// ---------------------------------------------------------------------------
__device__ __forceinline__ unsigned long long ffma2(unsigned long long a,
                                                    unsigned long long b,
                                                    unsigned long long c) {
    unsigned long long d;
    asm("fma.rn.f32x2 %0, %1, %2, %3;" : "=l"(d) : "l"(a), "l"(b), "l"(c));
    return d;
}
__device__ __forceinline__ unsigned long long bcast2(float v) {
    unsigned long long r;
    unsigned int u = __float_as_uint(v);
    asm("mov.b64 %0, {%1, %2};" : "=l"(r) : "r"(u), "r"(u));
    return r;
}
__device__ __forceinline__ float2 unpack2(unsigned long long v) {
    unsigned int lo, hi;
    asm("mov.b64 {%0, %1}, %2;" : "=r"(lo), "=r"(hi) : "l"(v));
    return make_float2(__uint_as_float(lo), __uint_as_float(hi));
}

// ---------------------------------------------------------------------------
// CSR build stage 0: zero counts
// ---------------------------------------------------------------------------
__global__ void zero_cnt_kernel() {
    int i = blockIdx.x * 256 + threadIdx.x;
    if (i < NTOT) g_cnt[i] = 0;
}

// ---------------------------------------------------------------------------
// CSR build stage 1: in-degree counts over all 6 directed relations.
// blockIdx.y = relation id (0..5). Int atomics: ~3M lanes (~8us L2-ALU).
// ---------------------------------------------------------------------------
__global__ void cnt_kernel(const int* __restrict__ pbs, const int* __restrict__ pbd,
                           const int* __restrict__ pcs, const int* __restrict__ pcd,
                           const int* __restrict__ pss, const int* __restrict__ psd) {
    int i = blockIdx.x * 256 + threadIdx.x;
    if (i >= EE) return;
    int d;
    switch (blockIdx.y) {
        case 0:  d = pbd[i] + BOFF; break;
        case 1:  d = pbs[i];        break;
        case 2:  d = pcd[i] + COFF; break;
        case 3:  d = pcs[i];        break;
        case 4:  d = psd[i] + SOFF; break;
        default: d = pss[i];        break;
    }
    atomicAdd(&g_cnt[d], 1);
}

// ---------------------------------------------------------------------------
// CSR build stage 2: exclusive scan of g_cnt (3-kernel scan)
// ---------------------------------------------------------------------------
__global__ void scan1_kernel() {            // per-1024-chunk reduction
    __shared__ int sm[1024];
    int t = threadIdx.x;
    int i = blockIdx.x * 1024 + t;
    sm[t] = (i < NTOT) ? g_cnt[i] : 0;
    __syncthreads();
    for (int s = 512; s > 0; s >>= 1) {
        if (t < s) sm[t] += sm[t + s];
        __syncthreads();
    }
    if (t == 0) g_bsum[blockIdx.x] = sm[0];
}

__global__ void scan2_kernel() {            // single-block scan of block sums
    __shared__ int sm[1024];
    int t = threadIdx.x;
    sm[t] = (t < SCAN_NB) ? g_bsum[t] : 0;
    __syncthreads();
    for (int off = 1; off < 1024; off <<= 1) {
        int u = (t >= off) ? sm[t - off] : 0;
        __syncthreads();
        sm[t] += u;
        __syncthreads();
    }
    if (t < SCAN_NB) g_bsum[t] = t ? sm[t - 1] : 0;   // exclusive
}

__global__ void scan3_kernel() {            // chunk scan + offsets; also 1/deg
    __shared__ int sm[1024];
    int t = threadIdx.x;
    int i = blockIdx.x * 1024 + t;
    int c = (i < NTOT) ? g_cnt[i] : 0;
    sm[t] = c;
    __syncthreads();
    for (int off = 1; off < 1024; off <<= 1) {
        int u = (t >= off) ? sm[t - off] : 0;
        __syncthreads();
        sm[t] += u;
        __syncthreads();
    }
    if (i < NTOT) {
        int excl = g_bsum[blockIdx.x] + sm[t] - c;
        g_row[i]  = excl;
        g_fill[i] = excl;
        g_deg[i]  = 1.0f / fmaxf((float)c, 1.0f);
    }
    if (i == NTOT - 1) g_row[NTOT] = E6;
}

// ---------------------------------------------------------------------------
// CSR build stage 3: fill adjacency (src index per slot)
// ---------------------------------------------------------------------------
__global__ void fill_kernel(const int* __restrict__ pbs, const int* __restrict__ pbd,
                            const int* __restrict__ pcs, const int* __restrict__ pcd,
                            const int* __restrict__ pss, const int* __restrict__ psd) {
    int i = blockIdx.x * 256 + threadIdx.x;
    if (i >= EE) return;
    int s, d;
    switch (blockIdx.y) {
        case 0:  s = pbs[i];        d = pbd[i] + BOFF; break;
        case 1:  s = pbd[i] + BOFF; d = pbs[i];        break;
        case 2:  s = pcs[i];        d = pcd[i] + COFF; break;
        case 3:  s = pcd[i] + COFF; d = pcs[i];        break;
        case 4:  s = pss[i];        d = psd[i] + SOFF; break;
        default: s = psd[i] + SOFF; d = pss[i];        break;
    }
    int pos = atomicAdd(&g_fill[d], 1);
    g_eidx[pos] = s;
}

// ---------------------------------------------------------------------------
// Atomic-free aggregation: warp per dst node, lane covers 2 cols (float2),
// 4 edges in flight for MLP. Writes every row (no pre-zero needed).
// ---------------------------------------------------------------------------
__global__ void agg_kernel(const float* __restrict__ x) {
    int w = (blockIdx.x * blockDim.x + threadIdx.x) >> 5;
    if (w >= NTOT) return;
    int lane = threadIdx.x & 31;
    const size_t co = (size_t)(lane * 2);

    int beg = g_row[w];
    int end = g_row[w + 1];
    float2 acc = make_float2(0.f, 0.f);

    int j = beg;
    for (; j + 3 < end; j += 4) {
        int s0 = g_eidx[j], s1 = g_eidx[j + 1], s2 = g_eidx[j + 2], s3 = g_eidx[j + 3];
        float2 v0 = *(const float2*)&x[(size_t)s0 * H + co];
        float2 v1 = *(const float2*)&x[(size_t)s1 * H + co];
        float2 v2 = *(const float2*)&x[(size_t)s2 * H + co];
        float2 v3 = *(const float2*)&x[(size_t)s3 * H + co];
        acc.x += v0.x + v1.x; acc.y += v0.y + v1.y;
        acc.x += v2.x + v3.x; acc.y += v2.y + v3.y;
    }
    for (; j < end; j++) {
        int s = g_eidx[j];
        float2 v = *(const float2*)&x[(size_t)s * H + co];
        acc.x += v.x; acc.y += v.y;
    }
    *(float2*)&g_agg[(size_t)w * H + co] = acc;
}

// ---------------------------------------------------------------------------
// Copy embeddings into g_x0 rows [NP, NTOT)
// ---------------------------------------------------------------------------
__global__ void copy_emb_kernel(const float* __restrict__ eb,
                                const float* __restrict__ ec,
                                const float* __restrict__ es) {
    int i = blockIdx.x * 256 + threadIdx.x;
    const int nb4 = NB * H / 4, nc4 = NCA * H / 4, ns4 = NSH * H / 4;
    float4* dst = reinterpret_cast<float4*>(g_x0 + (size_t)NP * H);
    if (i < nb4)
        dst[i] = reinterpret_cast<const float4*>(eb)[i];
    else if (i < nb4 + nc4)
        dst[i] = reinterpret_cast<const float4*>(ec)[i - nb4];
    else if (i < nb4 + nc4 + ns4)
        dst[i] = reinterpret_cast<const float4*>(es)[i - nb4 - nc4];
}

// ---------------------------------------------------------------------------
// Projection: g_x0[0:NP] = relu(x_product @ W_proj^T + b_proj)
// ---------------------------------------------------------------------------
#define PROJ_BR 128
#define PROJ_KT 16
#define PROJ_XS 20
#define PROJ_SMEM ((FIN * 64 + PROJ_BR * PROJ_XS) * 4)

__global__ void proj_kernel(const float* __restrict__ X,
                            const float* __restrict__ W,
                            const float* __restrict__ b) {
    extern __shared__ float sm[];
    float* WT = sm;                 // [384][64] k-major
    float* Xs = sm + FIN * 64;      // [128][PROJ_XS]
    const int t = threadIdx.x;

    for (int e = t; e < FIN * 64; e += 256) {
        int c = e & 63, k = e >> 6;
        WT[k * 64 + c] = W[c * FIN + k];
    }

    const int row0 = blockIdx.x * PROJ_BR;
    const int cg = t & 7;
    const int rg = t >> 3;

    unsigned long long acc[4][4];
#pragma unroll
    for (int i = 0; i < 4; i++)
#pragma unroll
        for (int j = 0; j < 4; j++) acc[i][j] = 0ull;

    for (int kt = 0; kt < FIN; kt += PROJ_KT) {
        __syncthreads();
        for (int e = t; e < PROJ_BR * 4; e += 256) {
            int r = e >> 2, q = (e & 3) * 4;
            int grow = row0 + r;
            if (grow >= NP) grow = NP - 1;
            *(float4*)&Xs[r * PROJ_XS + q] =
                *(const float4*)&X[(size_t)grow * FIN + kt + q];
        }
        __syncthreads();
#pragma unroll
        for (int kk = 0; kk < PROJ_KT; kk++) {
            const int k = kt + kk;
            const ulonglong2 w0 = *(const ulonglong2*)&WT[k * 64 + cg * 8];
            const ulonglong2 w1 = *(const ulonglong2*)&WT[k * 64 + cg * 8 + 4];
#pragma unroll
            for (int i = 0; i < 4; i++) {
                unsigned long long xv = bcast2(Xs[(rg + 32 * i) * PROJ_XS + kk]);
                acc[i][0] = ffma2(xv, w0.x, acc[i][0]);
                acc[i][1] = ffma2(xv, w0.y, acc[i][1]);
                acc[i][2] = ffma2(xv, w1.x, acc[i][2]);
                acc[i][3] = ffma2(xv, w1.y, acc[i][3]);
            }
        }
    }

    float bias[8];
#pragma unroll
    for (int j = 0; j < 8; j++) bias[j] = b[cg * 8 + j];
#pragma unroll
    for (int i = 0; i < 4; i++) {
        int grow = row0 + rg + 32 * i;
        if (grow < NP) {
            float o[8];
#pragma unroll
            for (int j = 0; j < 4; j++) {
                float2 p = unpack2(acc[i][j]);
                o[2 * j]     = fmaxf(p.x + bias[2 * j], 0.f);
                o[2 * j + 1] = fmaxf(p.y + bias[2 * j + 1], 0.f);
            }
            float* dst = &g_x0[(size_t)grow * H + cg * 8];
            *(float4*)dst       = make_float4(o[0], o[1], o[2], o[3]);
            *(float4*)(dst + 4) = make_float4(o[4], o[5], o[6], o[7]);
        }
    }
}

// ---------------------------------------------------------------------------
// SAGE combine: out = [relu]( (agg*inv) @ Wl^T + bl + x @ Wr^T )
// ---------------------------------------------------------------------------
template <int OUT, bool RELU>
__global__ void combine_kernel(const float* __restrict__ agg,
                               const float* __restrict__ x,
                               const float* __restrict__ Wl,
                               const float* __restrict__ bl,
                               const float* __restrict__ Wr,
                               float* __restrict__ out) {
    constexpr int BR = 128;
    constexpr int COLG = OUT / 8;
    constexpr int RG = 256 / COLG;
    constexpr int R = BR / RG;
    constexpr int STR = 68;

    extern __shared__ float sm[];
    float* WlT = sm;
    float* WrT = WlT + 64 * OUT;
    float* As  = WrT + 64 * OUT;
    float* Xs  = As + BR * STR;

    const int t = threadIdx.x;
    for (int e = t; e < 64 * OUT; e += 256) {
        int c = e % OUT, k = e / OUT;
        WlT[k * OUT + c] = Wl[c * 64 + k];
        WrT[k * OUT + c] = Wr[c * 64 + k];
    }

    const int row0 = blockIdx.x * BR;
    for (int e = t; e < BR * 16; e += 256) {
        int r = e >> 4, q = (e & 15) * 4;
        int grow = row0 + r;
        if (grow >= NTOT) grow = NTOT - 1;
        float iv = g_deg[grow];
        float4 av = *(const float4*)&agg[(size_t)grow * H + q];
        av.x *= iv; av.y *= iv; av.z *= iv; av.w *= iv;
        *(float4*)&As[r * STR + q] = av;
        *(float4*)&Xs[r * STR + q] = *(const float4*)&x[(size_t)grow * H + q];
    }
    __syncthreads();

    const int cg = t % COLG;
    const int rg = t / COLG;

    unsigned long long acc[R][4];
#pragma unroll
    for (int i = 0; i < R; i++)
#pragma unroll
        for (int j = 0; j < 4; j++) acc[i][j] = 0ull;

#pragma unroll 2
    for (int k = 0; k < 64; k++) {
        const ulonglong2 wl0 = *(const ulonglong2*)&WlT[k * OUT + cg * 8];
        const ulonglong2 wl1 = *(const ulonglong2*)&WlT[k * OUT + cg * 8 + 4];
        const ulonglong2 wr0 = *(const ulonglong2*)&WrT[k * OUT + cg * 8];
        const ulonglong2 wr1 = *(const ulonglong2*)&WrT[k * OUT + cg * 8 + 4];
#pragma unroll
        for (int i = 0; i < R; i++) {
            const int r = rg + RG * i;
            unsigned long long a2 = bcast2(As[r * STR + k]);
            unsigned long long x2 = bcast2(Xs[r * STR + k]);
            acc[i][0] = ffma2(a2, wl0.x, acc[i][0]);
            acc[i][0] = ffma2(x2, wr0.x, acc[i][0]);
            acc[i][1] = ffma2(a2, wl0.y, acc[i][1]);
            acc[i][1] = ffma2(x2, wr0.y, acc[i][1]);
            acc[i][2] = ffma2(a2, wl1.x, acc[i][2]);
            acc[i][2] = ffma2(x2, wr1.x, acc[i][2]);
            acc[i][3] = ffma2(a2, wl1.y, acc[i][3]);
            acc[i][3] = ffma2(x2, wr1.y, acc[i][3]);
        }
    }

    float bias[8];
#pragma unroll
    for (int j = 0; j < 8; j++) bias[j] = bl[cg * 8 + j];
#pragma unroll
    for (int i = 0; i < R; i++) {
        int grow = row0 + rg + RG * i;
        if (grow < NTOT) {
            float o[8];
#pragma unroll
            for (int j = 0; j < 4; j++) {
                float2 p = unpack2(acc[i][j]);
                float v0 = p.x + bias[2 * j];
                float v1 = p.y + bias[2 * j + 1];
                if (RELU) { v0 = fmaxf(v0, 0.f); v1 = fmaxf(v1, 0.f); }
                o[2 * j] = v0; o[2 * j + 1] = v1;
            }
            float* dst = &out[(size_t)grow * OUT + cg * 8];
            *(float4*)dst       = make_float4(o[0], o[1], o[2], o[3]);
            *(float4*)(dst + 4) = make_float4(o[4], o[5], o[6], o[7]);
        }
    }
}

// ---------------------------------------------------------------------------
// Host launch sequence (graph-capturable, allocation-free)
// ---------------------------------------------------------------------------
extern "C" void kernel_launch(void* const* d_in, const int* in_sizes, int n_in,
                              void* d_out, int out_size) {
    (void)in_sizes; (void)n_in; (void)out_size;

    const float* x_product = (const float*)d_in[0];
    const int*   pb_src    = (const int*)d_in[1];
    const int*   pb_dst    = (const int*)d_in[2];
    const int*   pc_src    = (const int*)d_in[3];
    const int*   pc_dst    = (const int*)d_in[4];
    const int*   ps_src    = (const int*)d_in[5];
    const int*   ps_dst    = (const int*)d_in[6];
    const float* W_proj    = (const float*)d_in[7];
    const float* b_proj    = (const float*)d_in[8];
    const float* emb_b     = (const float*)d_in[9];
    const float* emb_c     = (const float*)d_in[10];
    const float* emb_s     = (const float*)d_in[11];
    const float* W1l       = (const float*)d_in[12];
    const float* b1l       = (const float*)d_in[13];
    const float* W1r       = (const float*)d_in[14];
    const float* W2l       = (const float*)d_in[15];
    const float* b2l       = (const float*)d_in[16];
    const float* W2r       = (const float*)d_in[17];
    float* out = (float*)d_out;

    float *px0, *ph1, *pagg;
    cudaGetSymbolAddress((void**)&px0, g_x0);
    cudaGetSymbolAddress((void**)&ph1, g_h1);
    cudaGetSymbolAddress((void**)&pagg, g_agg);

    const int CMB64_SMEM = (64 * 64 * 2 + 128 * 68 * 2) * 4;   // 102400
    const int CMB32_SMEM = (64 * 32 * 2 + 128 * 68 * 2) * 4;   //  86016
    cudaFuncSetAttribute(proj_kernel,
                         cudaFuncAttributeMaxDynamicSharedMemorySize, PROJ_SMEM);
    cudaFuncSetAttribute(combine_kernel<64, true>,
                         cudaFuncAttributeMaxDynamicSharedMemorySize, CMB64_SMEM);
    cudaFuncSetAttribute(combine_kernel<32, false>,
                         cudaFuncAttributeMaxDynamicSharedMemorySize, CMB32_SMEM);

    const int IB  = (NTOT + 255) / 256;
    const int CPB = ((NB + NCA + NSH) * H / 4 + 255) / 256;
    const int PRB = (NP + PROJ_BR - 1) / PROJ_BR;
    const int CMB = (NTOT + 127) / 128;
    const int AGB = (NTOT + 7) / 8;          // 8 warps/block, warp per node
    const dim3 EG((EE + 255) / 256, 6);      // per-relation grid

    // --- CSR build (once; shared by both layers, also yields 1/deg) ---
    zero_cnt_kernel<<<IB, 256>>>();
    cnt_kernel<<<EG, 256>>>(pb_src, pb_dst, pc_src, pc_dst, ps_src, ps_dst);
    scan1_kernel<<<SCAN_NB, 1024>>>();
    scan2_kernel<<<1, 1024>>>();
    scan3_kernel<<<SCAN_NB, 1024>>>();
    fill_kernel<<<EG, 256>>>(pb_src, pb_dst, pc_src, pc_dst, ps_src, ps_dst);

    // --- node features ---
    proj_kernel<<<PRB, 256, PROJ_SMEM>>>(x_product, W_proj, b_proj);
    copy_emb_kernel<<<CPB, 256>>>(emb_b, emb_c, emb_s);

    // --- layer 1: gather-aggregate + combine (relu) ---
    agg_kernel<<<AGB, 256>>>(px0);
    combine_kernel<64, true><<<CMB, 256, CMB64_SMEM>>>(pagg, px0, W1l, b1l, W1r, ph1);

    // --- layer 2: gather-aggregate + combine -> d_out [N, 32] ---
    agg_kernel<<<AGB, 256>>>(ph1);
    combine_kernel<32, false><<<CMB, 256, CMB32_SMEM>>>(pagg, ph1, W2l, b2l, W2r, out);
}

// round 5
// speedup vs baseline: 1.2501x; 1.0104x over previous
#include <cuda_runtime.h>

// ---------------------------------------------------------------------------
// Problem constants (match reference)
// ---------------------------------------------------------------------------
#define NP   500000
#define NB   20000
#define NCA  5000
#define NSH  2000
#define NTOT 527000          // NP+NB+NCA+NSH
#define EE   500000          // edges per relation (one direction)
#define E6   (6 * EE)        // total directed edges
#define H    64
#define ODIM 32
#define FIN  384

#define BOFF NP
#define COFF (NP + NB)
#define SOFF (NP + NB + NCA)

#define SCAN_NB ((NTOT + 1023) / 1024)   // 515

// ---------------------------------------------------------------------------
// Scratch (device globals: allocation-free rule)
// ---------------------------------------------------------------------------
__device__ float g_x0[(size_t)NTOT * H];    // layer-0 features
__device__ float g_h1[(size_t)NTOT * H];    // layer-1 output
__device__ float g_agg[(size_t)NTOT * H];   // aggregation buffer (reused)
__device__ float g_deg[NTOT];               // 1/max(in-degree,1)
__device__ int   g_cnt[NTOT];               // in-degree counts
__device__ int   g_row[NTOT + 1];           // CSR row starts
__device__ int   g_fill[NTOT];              // fill cursors
__device__ int   g_eidx[E6];                // CSR src indices (dst-sorted)
__device__ int   g_bsum[SCAN_NB];           // scan block sums

// ---------------------------------------------------------------------------
// f32x2 packed-FMA helpers (Blackwell FFMA2)
// ---------------------------------------------------------------------------
__device__ __forceinline__ unsigned long long ffma2(unsigned long long a,
                                                    unsigned long long b,
                                                    unsigned long long c) {
    unsigned long long d;
    asm("fma.rn.f32x2 %0, %1, %2, %3;" : "=l"(d) : "l"(a), "l"(b), "l"(c));
    return d;
}
__device__ __forceinline__ unsigned long long bcast2(float v) {
    unsigned long long r;
    unsigned int u = __float_as_uint(v);
    asm("mov.b64 %0, {%1, %2};" : "=l"(r) : "r"(u), "r"(u));
    return r;
}
__device__ __forceinline__ float2 unpack2(unsigned long long v) {
    unsigned int lo, hi;
    asm("mov.b64 {%0, %1}, %2;" : "=r"(lo), "=r"(hi) : "l"(v));
    return make_float2(__uint_as_float(lo), __uint_as_float(hi));
}

// ---------------------------------------------------------------------------
// CSR stage 1: in-degree counts (g_cnt pre-zeroed via cudaMemsetAsync).
// blockIdx.y = relation id (0..5).
// ---------------------------------------------------------------------------
__global__ void cnt_kernel(const int* __restrict__ pbs, const int* __restrict__ pbd,
                           const int* __restrict__ pcs, const int* __restrict__ pcd,
                           const int* __restrict__ pss, const int* __restrict__ psd) {
    int i = blockIdx.x * 256 + threadIdx.x;
    if (i >= EE) return;
    int d;
    switch (blockIdx.y) {
        case 0:  d = pbd[i] + BOFF; break;
        case 1:  d = pbs[i];        break;
        case 2:  d = pcd[i] + COFF; break;
        case 3:  d = pcs[i];        break;
        case 4:  d = psd[i] + SOFF; break;
        default: d = pss[i];        break;
    }
    atomicAdd(&g_cnt[d], 1);
}

// ---------------------------------------------------------------------------
// CSR stage 2a: per-1024-chunk sums
// ---------------------------------------------------------------------------
__global__ void scan1_kernel() {
    __shared__ int sm[1024];
    int t = threadIdx.x;
    int i = blockIdx.x * 1024 + t;
    sm[t] = (i < NTOT) ? g_cnt[i] : 0;
    __syncthreads();
    for (int s = 512; s > 0; s >>= 1) {
        if (t < s) sm[t] += sm[t + s];
        __syncthreads();
    }
    if (t == 0) g_bsum[blockIdx.x] = sm[0];
}

// ---------------------------------------------------------------------------
// CSR stage 2b (fused): each block reduces block sums [0, bid) for its base,
// then scans its own 1024 counts. Also emits 1/deg and fill cursors.
// ---------------------------------------------------------------------------
__global__ void scan3_kernel() {
    __shared__ int sb[1024];
    __shared__ int base_sh;
    int t = threadIdx.x;

    int v = (t < SCAN_NB && t < (int)blockIdx.x) ? g_bsum[t] : 0;
    sb[t] = v;
    __syncthreads();
    for (int s = 512; s > 0; s >>= 1) {
        if (t < s) sb[t] += sb[t + s];
        __syncthreads();
    }
    if (t == 0) base_sh = sb[0];
    __syncthreads();
    int base = base_sh;
    __syncthreads();

    int i = blockIdx.x * 1024 + t;
    int c = (i < NTOT) ? g_cnt[i] : 0;
    sb[t] = c;
    __syncthreads();
    for (int off = 1; off < 1024; off <<= 1) {
        int u = (t >= off) ? sb[t - off] : 0;
        __syncthreads();
        sb[t] += u;
        __syncthreads();
    }
    if (i < NTOT) {
        int excl = base + sb[t] - c;
        g_row[i]  = excl;
        g_fill[i] = excl;
        g_deg[i]  = 1.0f / fmaxf((float)c, 1.0f);
    }
    if (i == NTOT - 1) g_row[NTOT] = E6;
}

// ---------------------------------------------------------------------------
// CSR stage 3: fill adjacency
// ---------------------------------------------------------------------------
__global__ void fill_kernel(const int* __restrict__ pbs, const int* __restrict__ pbd,
                            const int* __restrict__ pcs, const int* __restrict__ pcd,
                            const int* __restrict__ pss, const int* __restrict__ psd) {
    int i = blockIdx.x * 256 + threadIdx.x;
    if (i >= EE) return;
    int s, d;
    switch (blockIdx.y) {
        case 0:  s = pbs[i];        d = pbd[i] + BOFF; break;
        case 1:  s = pbd[i] + BOFF; d = pbs[i];        break;
        case 2:  s = pcs[i];        d = pcd[i] + COFF; break;
        case 3:  s = pcd[i] + COFF; d = pcs[i];        break;
        case 4:  s = pss[i];        d = psd[i] + SOFF; break;
        default: s = psd[i] + SOFF; d = pss[i];        break;
    }
    int pos = atomicAdd(&g_fill[d], 1);
    g_eidx[pos] = s;
}

// ---------------------------------------------------------------------------
// Atomic-free aggregation v2: warp per dst node, split into two 16-lane
// halves. Each half covers the full 256B row with float4 and processes
// alternating edges; unroll 4 => 8 edge-rows in flight per warp.
// Cross-half reduction via shfl.bfly at the end. Writes every row.
// ---------------------------------------------------------------------------
__global__ void agg_kernel(const float* __restrict__ x) {
    int w = (blockIdx.x * blockDim.x + threadIdx.x) >> 5;
    if (w >= NTOT) return;
    const int lane = threadIdx.x & 31;
    const int half = lane >> 4;
    const int li   = lane & 15;
    const size_t co = (size_t)(li * 4);

    const int beg = g_row[w];
    const int end = g_row[w + 1];

    float4 acc = make_float4(0.f, 0.f, 0.f, 0.f);

    int j = beg + half;
    for (; j + 6 < end; j += 8) {
        int s0 = g_eidx[j];
        int s1 = g_eidx[j + 2];
        int s2 = g_eidx[j + 4];
        int s3 = g_eidx[j + 6];
        float4 v0 = *(const float4*)&x[(size_t)s0 * H + co];
        float4 v1 = *(const float4*)&x[(size_t)s1 * H + co];
        float4 v2 = *(const float4*)&x[(size_t)s2 * H + co];
        float4 v3 = *(const float4*)&x[(size_t)s3 * H + co];
        acc.x += v0.x + v1.x + v2.x + v3.x;
        acc.y += v0.y + v1.y + v2.y + v3.y;
        acc.z += v0.z + v1.z + v2.z + v3.z;
        acc.w += v0.w + v1.w + v2.w + v3.w;
    }
    for (; j < end; j += 2) {
        int s = g_eidx[j];
        float4 v = *(const float4*)&x[(size_t)s * H + co];
        acc.x += v.x; acc.y += v.y; acc.z += v.z; acc.w += v.w;
    }

    acc.x += __shfl_xor_sync(0xffffffffu, acc.x, 16);
    acc.y += __shfl_xor_sync(0xffffffffu, acc.y, 16);
    acc.z += __shfl_xor_sync(0xffffffffu, acc.z, 16);
    acc.w += __shfl_xor_sync(0xffffffffu, acc.w, 16);

    if (half == 0)
        *(float4*)&g_agg[(size_t)w * H + co] = acc;
}

// ---------------------------------------------------------------------------
// Projection: g_x0[0:NP] = relu(x_product @ W_proj^T + b_proj)
// ---------------------------------------------------------------------------
#define PROJ_BR 128
#define PROJ_KT 16
#define PROJ_XS 20
#define PROJ_SMEM ((FIN * 64 + PROJ_BR * PROJ_XS) * 4)

__global__ void proj_kernel(const float* __restrict__ X,
                            const float* __restrict__ W,
                            const float* __restrict__ b) {
    extern __shared__ float sm[];
    float* WT = sm;                 // [384][64] k-major
    float* Xs = sm + FIN * 64;      // [128][PROJ_XS]
    const int t = threadIdx.x;

    for (int e = t; e < FIN * 64; e += 256) {
        int c = e & 63, k = e >> 6;
        WT[k * 64 + c] = W[c * FIN + k];
    }

    const int row0 = blockIdx.x * PROJ_BR;
    const int cg = t & 7;
    const int rg = t >> 3;

    unsigned long long acc[4][4];
#pragma unroll
    for (int i = 0; i < 4; i++)
#pragma unroll
        for (int j = 0; j < 4; j++) acc[i][j] = 0ull;

    for (int kt = 0; kt < FIN; kt += PROJ_KT) {
        __syncthreads();
        for (int e = t; e < PROJ_BR * 4; e += 256) {
            int r = e >> 2, q = (e & 3) * 4;
            int grow = row0 + r;
            if (grow >= NP) grow = NP - 1;
            *(float4*)&Xs[r * PROJ_XS + q] =
                *(const float4*)&X[(size_t)grow * FIN + kt + q];
        }
        __syncthreads();
#pragma unroll
        for (int kk = 0; kk < PROJ_KT; kk++) {
            const int k = kt + kk;
            const ulonglong2 w0 = *(const ulonglong2*)&WT[k * 64 + cg * 8];
            const ulonglong2 w1 = *(const ulonglong2*)&WT[k * 64 + cg * 8 + 4];
#pragma unroll
            for (int i = 0; i < 4; i++) {
                unsigned long long xv = bcast2(Xs[(rg + 32 * i) * PROJ_XS + kk]);
                acc[i][0] = ffma2(xv, w0.x, acc[i][0]);
                acc[i][1] = ffma2(xv, w0.y, acc[i][1]);
                acc[i][2] = ffma2(xv, w1.x, acc[i][2]);
                acc[i][3] = ffma2(xv, w1.y, acc[i][3]);
            }
        }
    }

    float bias[8];
#pragma unroll
    for (int j = 0; j < 8; j++) bias[j] = b[cg * 8 + j];
#pragma unroll
    for (int i = 0; i < 4; i++) {
        int grow = row0 + rg + 32 * i;
        if (grow < NP) {
            float o[8];
#pragma unroll
            for (int j = 0; j < 4; j++) {
                float2 p = unpack2(acc[i][j]);
                o[2 * j]     = fmaxf(p.x + bias[2 * j], 0.f);
                o[2 * j + 1] = fmaxf(p.y + bias[2 * j + 1], 0.f);
            }
            float* dst = &g_x0[(size_t)grow * H + cg * 8];
            *(float4*)dst       = make_float4(o[0], o[1], o[2], o[3]);
            *(float4*)(dst + 4) = make_float4(o[4], o[5], o[6], o[7]);
        }
    }
}

// ---------------------------------------------------------------------------
// SAGE combine: out = [relu]( (agg*inv) @ Wl^T + bl + x @ Wr^T )
// ---------------------------------------------------------------------------
template <int OUT, bool RELU>
__global__ void combine_kernel(const float* __restrict__ agg,
                               const float* __restrict__ x,
                               const float* __restrict__ Wl,
                               const float* __restrict__ bl,
                               const float* __restrict__ Wr,
                               float* __restrict__ out) {
    constexpr int BR = 128;
    constexpr int COLG = OUT / 8;
    constexpr int RG = 256 / COLG;
    constexpr int R = BR / RG;
    constexpr int STR = 68;

    extern __shared__ float sm[];
    float* WlT = sm;
    float* WrT = WlT + 64 * OUT;
    float* As  = WrT + 64 * OUT;
    float* Xs  = As + BR * STR;

    const int t = threadIdx.x;
    for (int e = t; e < 64 * OUT; e += 256) {
        int c = e % OUT, k = e / OUT;
        WlT[k * OUT + c] = Wl[c * 64 + k];
        WrT[k * OUT + c] = Wr[c * 64 + k];
    }

    const int row0 = blockIdx.x * BR;
    for (int e = t; e < BR * 16; e += 256) {
        int r = e >> 4, q = (e & 15) * 4;
        int grow = row0 + r;
        if (grow >= NTOT) grow = NTOT - 1;
        float iv = g_deg[grow];
        float4 av = *(const float4*)&agg[(size_t)grow * H + q];
        av.x *= iv; av.y *= iv; av.z *= iv; av.w *= iv;
        *(float4*)&As[r * STR + q] = av;
        *(float4*)&Xs[r * STR + q] = *(const float4*)&x[(size_t)grow * H + q];
    }
    __syncthreads();

    const int cg = t % COLG;
    const int rg = t / COLG;

    unsigned long long acc[R][4];
#pragma unroll
    for (int i = 0; i < R; i++)
#pragma unroll
        for (int j = 0; j < 4; j++) acc[i][j] = 0ull;

#pragma unroll 2
    for (int k = 0; k < 64; k++) {
        const ulonglong2 wl0 = *(const ulonglong2*)&WlT[k * OUT + cg * 8];
        const ulonglong2 wl1 = *(const ulonglong2*)&WlT[k * OUT + cg * 8 + 4];
        const ulonglong2 wr0 = *(const ulonglong2*)&WrT[k * OUT + cg * 8];
        const ulonglong2 wr1 = *(const ulonglong2*)&WrT[k * OUT + cg * 8 + 4];
#pragma unroll
        for (int i = 0; i < R; i++) {
            const int r = rg + RG * i;
            unsigned long long a2 = bcast2(As[r * STR + k]);
            unsigned long long x2 = bcast2(Xs[r * STR + k]);
            acc[i][0] = ffma2(a2, wl0.x, acc[i][0]);
            acc[i][0] = ffma2(x2, wr0.x, acc[i][0]);
            acc[i][1] = ffma2(a2, wl0.y, acc[i][1]);
            acc[i][1] = ffma2(x2, wr0.y, acc[i][1]);
            acc[i][2] = ffma2(a2, wl1.x, acc[i][2]);
            acc[i][2] = ffma2(x2, wr1.x, acc[i][2]);
            acc[i][3] = ffma2(a2, wl1.y, acc[i][3]);
            acc[i][3] = ffma2(x2, wr1.y, acc[i][3]);
        }
    }

    float bias[8];
#pragma unroll
    for (int j = 0; j < 8; j++) bias[j] = bl[cg * 8 + j];
#pragma unroll
    for (int i = 0; i < R; i++) {
        int grow = row0 + rg + RG * i;
        if (grow < NTOT) {
            float o[8];
#pragma unroll
            for (int j = 0; j < 4; j++) {
                float2 p = unpack2(acc[i][j]);
                float v0 = p.x + bias[2 * j];
                float v1 = p.y + bias[2 * j + 1];
                if (RELU) { v0 = fmaxf(v0, 0.f); v1 = fmaxf(v1, 0.f); }
                o[2 * j] = v0; o[2 * j + 1] = v1;
            }
            float* dst = &out[(size_t)grow * OUT + cg * 8];
            *(float4*)dst       = make_float4(o[0], o[1], o[2], o[3]);
            *(float4*)(dst + 4) = make_float4(o[4], o[5], o[6], o[7]);
        }
    }
}

// ---------------------------------------------------------------------------
// Host launch sequence (graph-capturable, allocation-free).
// Kernel-launch order is chosen so ncu's "-s 5 -c 1" captures agg_kernel
// (layer 1): proj(0) cnt(1) scan1(2) scan3(3) fill(4) agg1(5) cmb1(6)
// agg2(7) cmb2(8). memset/memcpy are graph memory nodes, not launches.
// ---------------------------------------------------------------------------
extern "C" void kernel_launch(void* const* d_in, const int* in_sizes, int n_in,
                              void* d_out, int out_size) {
    (void)in_sizes; (void)n_in; (void)out_size;

    const float* x_product = (const float*)d_in[0];
    const int*   pb_src    = (const int*)d_in[1];
    const int*   pb_dst    = (const int*)d_in[2];
    const int*   pc_src    = (const int*)d_in[3];
    const int*   pc_dst    = (const int*)d_in[4];
    const int*   ps_src    = (const int*)d_in[5];
    const int*   ps_dst    = (const int*)d_in[6];
    const float* W_proj    = (const float*)d_in[7];
    const float* b_proj    = (const float*)d_in[8];
    const float* emb_b     = (const float*)d_in[9];
    const float* emb_c     = (const float*)d_in[10];
    const float* emb_s     = (const float*)d_in[11];
    const float* W1l       = (const float*)d_in[12];
    const float* b1l       = (const float*)d_in[13];
    const float* W1r       = (const float*)d_in[14];
    const float* W2l       = (const float*)d_in[15];
    const float* b2l       = (const float*)d_in[16];
    const float* W2r       = (const float*)d_in[17];
    float* out = (float*)d_out;

    float *px0, *ph1, *pagg;
    int *pcnt;
    cudaGetSymbolAddress((void**)&px0, g_x0);
    cudaGetSymbolAddress((void**)&ph1, g_h1);
    cudaGetSymbolAddress((void**)&pagg, g_agg);
    cudaGetSymbolAddress((void**)&pcnt, g_cnt);

    const int CMB64_SMEM = (64 * 64 * 2 + 128 * 68 * 2) * 4;   // 102400
    const int CMB32_SMEM = (64 * 32 * 2 + 128 * 68 * 2) * 4;   //  86016
    cudaFuncSetAttribute(proj_kernel,
                         cudaFuncAttributeMaxDynamicSharedMemorySize, PROJ_SMEM);
    cudaFuncSetAttribute(combine_kernel<64, true>,
                         cudaFuncAttributeMaxDynamicSharedMemorySize, CMB64_SMEM);
    cudaFuncSetAttribute(combine_kernel<32, false>,
                         cudaFuncAttributeMaxDynamicSharedMemorySize, CMB32_SMEM);

    const int PRB = (NP + PROJ_BR - 1) / PROJ_BR;
    const int CMB = (NTOT + 127) / 128;
    const int AGB = (NTOT + 7) / 8;          // warp per node, 8 warps/block
    const dim3 EG((EE + 255) / 256, 6);      // per-relation grid

    // memory nodes (not kernel launches): zero counts, copy embeddings
    cudaMemsetAsync(pcnt, 0, NTOT * sizeof(int));
    cudaMemcpyAsync(px0 + (size_t)NP * H, emb_b,
                    (size_t)NB * H * sizeof(float), cudaMemcpyDeviceToDevice);
    cudaMemcpyAsync(px0 + (size_t)COFF * H, emb_c,
                    (size_t)NCA * H * sizeof(float), cudaMemcpyDeviceToDevice);
    cudaMemcpyAsync(px0 + (size_t)SOFF * H, emb_s,
                    (size_t)NSH * H * sizeof(float), cudaMemcpyDeviceToDevice);

    // launch 0: projection (independent of CSR)
    proj_kernel<<<PRB, 256, PROJ_SMEM>>>(x_product, W_proj, b_proj);

    // launches 1-4: CSR build (counts -> fused scan -> fill)
    cnt_kernel<<<EG, 256>>>(pb_src, pb_dst, pc_src, pc_dst, ps_src, ps_dst);
    scan1_kernel<<<SCAN_NB, 1024>>>();
    scan3_kernel<<<SCAN_NB, 1024>>>();
    fill_kernel<<<EG, 256>>>(pb_src, pb_dst, pc_src, pc_dst, ps_src, ps_dst);

    // launch 5: layer-1 aggregation  (ncu -s 5 captures THIS)
    agg_kernel<<<AGB, 256>>>(px0);
    // launch 6: layer-1 combine (relu)
    combine_kernel<64, true><<<CMB, 256, CMB64_SMEM>>>(pagg, px0, W1l, b1l, W1r, ph1);

    // launches 7-8: layer 2 -> d_out [N, 32]
    agg_kernel<<<AGB, 256>>>(ph1);
    combine_kernel<32, false><<<CMB, 256, CMB32_SMEM>>>(pagg, ph1, W2l, b2l, W2r, out);
}

// round 6
// speedup vs baseline: 1.2544x; 1.0034x over previous
#include <cuda_runtime.h>

// ---------------------------------------------------------------------------
// Problem constants (match reference)
// ---------------------------------------------------------------------------
#define NP   500000
#define NB   20000
#define NCA  5000
#define NSH  2000
#define NTOT 527000          // NP+NB+NCA+NSH
#define EE   500000          // edges per relation (one direction)
#define E6   (6 * EE)        // total directed edges
#define H    64
#define ODIM 32
#define FIN  384

#define BOFF NP
#define COFF (NP + NB)
#define SOFF (NP + NB + NCA)

#define SCAN_NB ((NTOT + 1023) / 1024)   // 515

// ---------------------------------------------------------------------------
// Scratch (device globals: allocation-free rule)
// ---------------------------------------------------------------------------
__device__ float g_x0[(size_t)NTOT * H];    // layer-0 features
__device__ float g_h1[(size_t)NTOT * H];    // layer-1 output
__device__ float g_agg[(size_t)NTOT * H];   // aggregation buffer (reused)
__device__ float g_deg[NTOT];               // 1/max(in-degree,1)
__device__ int   g_cnt[NTOT];               // in-degree counts
__device__ int   g_row[NTOT + 1];           // CSR row starts
__device__ int   g_fill[NTOT];              // fill cursors
__device__ int   g_eidx[E6];                // CSR src indices (dst-sorted)
__device__ int   g_bsum[SCAN_NB];           // scan block sums

// ---------------------------------------------------------------------------
// f32x2 packed-FMA helpers (Blackwell FFMA2)
// ---------------------------------------------------------------------------
__device__ __forceinline__ unsigned long long ffma2(unsigned long long a,
                                                    unsigned long long b,
                                                    unsigned long long c) {
    unsigned long long d;
    asm("fma.rn.f32x2 %0, %1, %2, %3;" : "=l"(d) : "l"(a), "l"(b), "l"(c));
    return d;
}
__device__ __forceinline__ unsigned long long bcast2(float v) {
    unsigned long long r;
    unsigned int u = __float_as_uint(v);
    asm("mov.b64 %0, {%1, %2};" : "=l"(r) : "r"(u), "r"(u));
    return r;
}
__device__ __forceinline__ float2 unpack2(unsigned long long v) {
    unsigned int lo, hi;
    asm("mov.b64 {%0, %1}, %2;" : "=r"(lo), "=r"(hi) : "l"(v));
    return make_float2(__uint_as_float(lo), __uint_as_float(hi));
}

// ---------------------------------------------------------------------------
// CSR stage 1: in-degree counts (g_cnt pre-zeroed via cudaMemsetAsync).
// blockIdx.y = relation id (0..5).
// ---------------------------------------------------------------------------
__global__ void cnt_kernel(const int* __restrict__ pbs, const int* __restrict__ pbd,
                           const int* __restrict__ pcs, const int* __restrict__ pcd,
                           const int* __restrict__ pss, const int* __restrict__ psd) {
    int i = blockIdx.x * 256 + threadIdx.x;
    if (i >= EE) return;
    int d;
    switch (blockIdx.y) {
        case 0:  d = pbd[i] + BOFF; break;
        case 1:  d = pbs[i];        break;
        case 2:  d = pcd[i] + COFF; break;
        case 3:  d = pcs[i];        break;
        case 4:  d = psd[i] + SOFF; break;
        default: d = pss[i];        break;
    }
    atomicAdd(&g_cnt[d], 1);
}

// ---------------------------------------------------------------------------
// CSR stage 2a: per-1024-chunk sums
// ---------------------------------------------------------------------------
__global__ void scan1_kernel() {
    __shared__ int sm[1024];
    int t = threadIdx.x;
    int i = blockIdx.x * 1024 + t;
    sm[t] = (i < NTOT) ? g_cnt[i] : 0;
    __syncthreads();
    for (int s = 512; s > 0; s >>= 1) {
        if (t < s) sm[t] += sm[t + s];
        __syncthreads();
    }
    if (t == 0) g_bsum[blockIdx.x] = sm[0];
}

// ---------------------------------------------------------------------------
// CSR stage 2b (fused): each block reduces block sums [0, bid) for its base,
// then scans its own 1024 counts. Also emits 1/deg and fill cursors.
// ---------------------------------------------------------------------------
__global__ void scan3_kernel() {
    __shared__ int sb[1024];
    __shared__ int base_sh;
    int t = threadIdx.x;

    int v = (t < SCAN_NB && t < (int)blockIdx.x) ? g_bsum[t] : 0;
    sb[t] = v;
    __syncthreads();
    for (int s = 512; s > 0; s >>= 1) {
        if (t < s) sb[t] += sb[t + s];
        __syncthreads();
    }
    if (t == 0) base_sh = sb[0];
    __syncthreads();
    int base = base_sh;
    __syncthreads();

    int i = blockIdx.x * 1024 + t;
    int c = (i < NTOT) ? g_cnt[i] : 0;
    sb[t] = c;
    __syncthreads();
    for (int off = 1; off < 1024; off <<= 1) {
        int u = (t >= off) ? sb[t - off] : 0;
        __syncthreads();
        sb[t] += u;
        __syncthreads();
    }
    if (i < NTOT) {
        int excl = base + sb[t] - c;
        g_row[i]  = excl;
        g_fill[i] = excl;
        g_deg[i]  = 1.0f / fmaxf((float)c, 1.0f);
    }
    if (i == NTOT - 1) g_row[NTOT] = E6;
}

// ---------------------------------------------------------------------------
// CSR stage 3: fill adjacency
// ---------------------------------------------------------------------------
__global__ void fill_kernel(const int* __restrict__ pbs, const int* __restrict__ pbd,
                            const int* __restrict__ pcs, const int* __restrict__ pcd,
                            const int* __restrict__ pss, const int* __restrict__ psd) {
    int i = blockIdx.x * 256 + threadIdx.x;
    if (i >= EE) return;
    int s, d;
    switch (blockIdx.y) {
        case 0:  s = pbs[i];        d = pbd[i] + BOFF; break;
        case 1:  s = pbd[i] + BOFF; d = pbs[i];        break;
        case 2:  s = pcs[i];        d = pcd[i] + COFF; break;
        case 3:  s = pcd[i] + COFF; d = pcs[i];        break;
        case 4:  s = pss[i];        d = psd[i] + SOFF; break;
        default: s = psd[i] + SOFF; d = pss[i];        break;
    }
    int pos = atomicAdd(&g_fill[d], 1);
    g_eidx[pos] = s;
}

// ---------------------------------------------------------------------------
// Atomic-free aggregation v2: warp per dst node, split into two 16-lane
// halves. Each half covers the full 256B row with float4 and processes
// alternating edges; unroll 4 => 8 edge-rows in flight per warp.
// Cross-half reduction via shfl.bfly at the end. Writes every row.
// ---------------------------------------------------------------------------
__global__ void agg_kernel(const float* __restrict__ x) {
    int w = (blockIdx.x * blockDim.x + threadIdx.x) >> 5;
    if (w >= NTOT) return;
    const int lane = threadIdx.x & 31;
    const int half = lane >> 4;
    const int li   = lane & 15;
    const size_t co = (size_t)(li * 4);

    const int beg = g_row[w];
    const int end = g_row[w + 1];

    float4 acc = make_float4(0.f, 0.f, 0.f, 0.f);

    int j = beg + half;
    for (; j + 6 < end; j += 8) {
        int s0 = g_eidx[j];
        int s1 = g_eidx[j + 2];
        int s2 = g_eidx[j + 4];
        int s3 = g_eidx[j + 6];
        float4 v0 = *(const float4*)&x[(size_t)s0 * H + co];
        float4 v1 = *(const float4*)&x[(size_t)s1 * H + co];
        float4 v2 = *(const float4*)&x[(size_t)s2 * H + co];
        float4 v3 = *(const float4*)&x[(size_t)s3 * H + co];
        acc.x += v0.x + v1.x + v2.x + v3.x;
        acc.y += v0.y + v1.y + v2.y + v3.y;
        acc.z += v0.z + v1.z + v2.z + v3.z;
        acc.w += v0.w + v1.w + v2.w + v3.w;
    }
    for (; j < end; j += 2) {
        int s = g_eidx[j];
        float4 v = *(const float4*)&x[(size_t)s * H + co];
        acc.x += v.x; acc.y += v.y; acc.z += v.z; acc.w += v.w;
    }

    acc.x += __shfl_xor_sync(0xffffffffu, acc.x, 16);
    acc.y += __shfl_xor_sync(0xffffffffu, acc.y, 16);
    acc.z += __shfl_xor_sync(0xffffffffu, acc.z, 16);
    acc.w += __shfl_xor_sync(0xffffffffu, acc.w, 16);

    if (half == 0)
        *(float4*)&g_agg[(size_t)w * H + co] = acc;
}

// ---------------------------------------------------------------------------
// Projection: g_x0[0:NP] = relu(x_product @ W_proj^T + b_proj)
// ---------------------------------------------------------------------------
#define PROJ_BR 128
#define PROJ_KT 16
#define PROJ_XS 20
#define PROJ_SMEM ((FIN * 64 + PROJ_BR * PROJ_XS) * 4)

__global__ void proj_kernel(const float* __restrict__ X,
                            const float* __restrict__ W,
                            const float* __restrict__ b) {
    extern __shared__ float sm[];
    float* WT = sm;                 // [384][64] k-major
    float* Xs = sm + FIN * 64;      // [128][PROJ_XS]
    const int t = threadIdx.x;

    for (int e = t; e < FIN * 64; e += 256) {
        int c = e & 63, k = e >> 6;
        WT[k * 64 + c] = W[c * FIN + k];
    }

    const int row0 = blockIdx.x * PROJ_BR;
    const int cg = t & 7;
    const int rg = t >> 3;

    unsigned long long acc[4][4];
#pragma unroll
    for (int i = 0; i < 4; i++)
#pragma unroll
        for (int j = 0; j < 4; j++) acc[i][j] = 0ull;

    for (int kt = 0; kt < FIN; kt += PROJ_KT) {
        __syncthreads();
        for (int e = t; e < PROJ_BR * 4; e += 256) {
            int r = e >> 2, q = (e & 3) * 4;
            int grow = row0 + r;
            if (grow >= NP) grow = NP - 1;
            *(float4*)&Xs[r * PROJ_XS + q] =
                *(const float4*)&X[(size_t)grow * FIN + kt + q];
        }
        __syncthreads();
#pragma unroll
        for (int kk = 0; kk < PROJ_KT; kk++) {
            const int k = kt + kk;
            const ulonglong2 w0 = *(const ulonglong2*)&WT[k * 64 + cg * 8];
            const ulonglong2 w1 = *(const ulonglong2*)&WT[k * 64 + cg * 8 + 4];
#pragma unroll
            for (int i = 0; i < 4; i++) {
                unsigned long long xv = bcast2(Xs[(rg + 32 * i) * PROJ_XS + kk]);
                acc[i][0] = ffma2(xv, w0.x, acc[i][0]);
                acc[i][1] = ffma2(xv, w0.y, acc[i][1]);
                acc[i][2] = ffma2(xv, w1.x, acc[i][2]);
                acc[i][3] = ffma2(xv, w1.y, acc[i][3]);
            }
        }
    }

    float bias[8];
#pragma unroll
    for (int j = 0; j < 8; j++) bias[j] = b[cg * 8 + j];
#pragma unroll
    for (int i = 0; i < 4; i++) {
        int grow = row0 + rg + 32 * i;
        if (grow < NP) {
            float o[8];
#pragma unroll
            for (int j = 0; j < 4; j++) {
                float2 p = unpack2(acc[i][j]);
                o[2 * j]     = fmaxf(p.x + bias[2 * j], 0.f);
                o[2 * j + 1] = fmaxf(p.y + bias[2 * j + 1], 0.f);
            }
            float* dst = &g_x0[(size_t)grow * H + cg * 8];
            *(float4*)dst       = make_float4(o[0], o[1], o[2], o[3]);
            *(float4*)(dst + 4) = make_float4(o[4], o[5], o[6], o[7]);
        }
    }
}

// ---------------------------------------------------------------------------
// SAGE combine: out = [relu]( (agg*inv) @ Wl^T + bl + x @ Wr^T )
// ---------------------------------------------------------------------------
template <int OUT, bool RELU>
__global__ void combine_kernel(const float* __restrict__ agg,
                               const float* __restrict__ x,
                               const float* __restrict__ Wl,
                               const float* __restrict__ bl,
                               const float* __restrict__ Wr,
                               float* __restrict__ out) {
    constexpr int BR = 128;
    constexpr int COLG = OUT / 8;
    constexpr int RG = 256 / COLG;
    constexpr int R = BR / RG;
    constexpr int STR = 68;

    extern __shared__ float sm[];
    float* WlT = sm;
    float* WrT = WlT + 64 * OUT;
    float* As  = WrT + 64 * OUT;
    float* Xs  = As + BR * STR;

    const int t = threadIdx.x;
    for (int e = t; e < 64 * OUT; e += 256) {
        int c = e % OUT, k = e / OUT;
        WlT[k * OUT + c] = Wl[c * 64 + k];
        WrT[k * OUT + c] = Wr[c * 64 + k];
    }

    const int row0 = blockIdx.x * BR;
    for (int e = t; e < BR * 16; e += 256) {
        int r = e >> 4, q = (e & 15) * 4;
        int grow = row0 + r;
        if (grow >= NTOT) grow = NTOT - 1;
        float iv = g_deg[grow];
        float4 av = *(const float4*)&agg[(size_t)grow * H + q];
        av.x *= iv; av.y *= iv; av.z *= iv; av.w *= iv;
        *(float4*)&As[r * STR + q] = av;
        *(float4*)&Xs[r * STR + q] = *(const float4*)&x[(size_t)grow * H + q];
    }
    __syncthreads();

    const int cg = t % COLG;
    const int rg = t / COLG;

    unsigned long long acc[R][4];
#pragma unroll
    for (int i = 0; i < R; i++)
#pragma unroll
        for (int j = 0; j < 4; j++) acc[i][j] = 0ull;

#pragma unroll 2
    for (int k = 0; k < 64; k++) {
        const ulonglong2 wl0 = *(const ulonglong2*)&WlT[k * OUT + cg * 8];
        const ulonglong2 wl1 = *(const ulonglong2*)&WlT[k * OUT + cg * 8 + 4];
        const ulonglong2 wr0 = *(const ulonglong2*)&WrT[k * OUT + cg * 8];
        const ulonglong2 wr1 = *(const ulonglong2*)&WrT[k * OUT + cg * 8 + 4];
#pragma unroll
        for (int i = 0; i < R; i++) {
            const int r = rg + RG * i;
            unsigned long long a2 = bcast2(As[r * STR + k]);
            unsigned long long x2 = bcast2(Xs[r * STR + k]);
            acc[i][0] = ffma2(a2, wl0.x, acc[i][0]);
            acc[i][0] = ffma2(x2, wr0.x, acc[i][0]);
            acc[i][1] = ffma2(a2, wl0.y, acc[i][1]);
            acc[i][1] = ffma2(x2, wr0.y, acc[i][1]);
            acc[i][2] = ffma2(a2, wl1.x, acc[i][2]);
            acc[i][2] = ffma2(x2, wr1.x, acc[i][2]);
            acc[i][3] = ffma2(a2, wl1.y, acc[i][3]);
            acc[i][3] = ffma2(x2, wr1.y, acc[i][3]);
        }
    }

    float bias[8];
#pragma unroll
    for (int j = 0; j < 8; j++) bias[j] = bl[cg * 8 + j];
#pragma unroll
    for (int i = 0; i < R; i++) {
        int grow = row0 + rg + RG * i;
        if (grow < NTOT) {
            float o[8];
#pragma unroll
            for (int j = 0; j < 4; j++) {
                float2 p = unpack2(acc[i][j]);
                float v0 = p.x + bias[2 * j];
                float v1 = p.y + bias[2 * j + 1];
                if (RELU) { v0 = fmaxf(v0, 0.f); v1 = fmaxf(v1, 0.f); }
                o[2 * j] = v0; o[2 * j + 1] = v1;
            }
            float* dst = &out[(size_t)grow * OUT + cg * 8];
            *(float4*)dst       = make_float4(o[0], o[1], o[2], o[3]);
            *(float4*)(dst + 4) = make_float4(o[4], o[5], o[6], o[7]);
        }
    }
}

// ---------------------------------------------------------------------------
// Host launch sequence (graph-capturable, allocation-free).
// Kernel-launch order is chosen so ncu's "-s 5 -c 1" captures agg_kernel
// (layer 1): proj(0) cnt(1) scan1(2) scan3(3) fill(4) agg1(5) cmb1(6)
// agg2(7) cmb2(8). memset/memcpy are graph memory nodes, not launches.
// ---------------------------------------------------------------------------
extern "C" void kernel_launch(void* const* d_in, const int* in_sizes, int n_in,
                              void* d_out, int out_size) {
    (void)in_sizes; (void)n_in; (void)out_size;

    const float* x_product = (const float*)d_in[0];
    const int*   pb_src    = (const int*)d_in[1];
    const int*   pb_dst    = (const int*)d_in[2];
    const int*   pc_src    = (const int*)d_in[3];
    const int*   pc_dst    = (const int*)d_in[4];
    const int*   ps_src    = (const int*)d_in[5];
    const int*   ps_dst    = (const int*)d_in[6];
    const float* W_proj    = (const float*)d_in[7];
    const float* b_proj    = (const float*)d_in[8];
    const float* emb_b     = (const float*)d_in[9];
    const float* emb_c     = (const float*)d_in[10];
    const float* emb_s     = (const float*)d_in[11];
    const float* W1l       = (const float*)d_in[12];
    const float* b1l       = (const float*)d_in[13];
    const float* W1r       = (const float*)d_in[14];
    const float* W2l       = (const float*)d_in[15];
    const float* b2l       = (const float*)d_in[16];
    const float* W2r       = (const float*)d_in[17];
    float* out = (float*)d_out;

    float *px0, *ph1, *pagg;
    int *pcnt;
    cudaGetSymbolAddress((void**)&px0, g_x0);
    cudaGetSymbolAddress((void**)&ph1, g_h1);
    cudaGetSymbolAddress((void**)&pagg, g_agg);
    cudaGetSymbolAddress((void**)&pcnt, g_cnt);

    const int CMB64_SMEM = (64 * 64 * 2 + 128 * 68 * 2) * 4;   // 102400
    const int CMB32_SMEM = (64 * 32 * 2 + 128 * 68 * 2) * 4;   //  86016
    cudaFuncSetAttribute(proj_kernel,
                         cudaFuncAttributeMaxDynamicSharedMemorySize, PROJ_SMEM);
    cudaFuncSetAttribute(combine_kernel<64, true>,
                         cudaFuncAttributeMaxDynamicSharedMemorySize, CMB64_SMEM);
    cudaFuncSetAttribute(combine_kernel<32, false>,
                         cudaFuncAttributeMaxDynamicSharedMemorySize, CMB32_SMEM);

    const int PRB = (NP + PROJ_BR - 1) / PROJ_BR;
    const int CMB = (NTOT + 127) / 128;
    const int AGB = (NTOT + 7) / 8;          // warp per node, 8 warps/block
    const dim3 EG((EE + 255) / 256, 6);      // per-relation grid

    // memory nodes (not kernel launches): zero counts, copy embeddings
    cudaMemsetAsync(pcnt, 0, NTOT * sizeof(int));
    cudaMemcpyAsync(px0 + (size_t)NP * H, emb_b,
                    (size_t)NB * H * sizeof(float), cudaMemcpyDeviceToDevice);
    cudaMemcpyAsync(px0 + (size_t)COFF * H, emb_c,
                    (size_t)NCA * H * sizeof(float), cudaMemcpyDeviceToDevice);
    cudaMemcpyAsync(px0 + (size_t)SOFF * H, emb_s,
                    (size_t)NSH * H * sizeof(float), cudaMemcpyDeviceToDevice);

    // launch 0: projection (independent of CSR)
    proj_kernel<<<PRB, 256, PROJ_SMEM>>>(x_product, W_proj, b_proj);

    // launches 1-4: CSR build (counts -> fused scan -> fill)
    cnt_kernel<<<EG, 256>>>(pb_src, pb_dst, pc_src, pc_dst, ps_src, ps_dst);
    scan1_kernel<<<SCAN_NB, 1024>>>();
    scan3_kernel<<<SCAN_NB, 1024>>>();
    fill_kernel<<<EG, 256>>>(pb_src, pb_dst, pc_src, pc_dst, ps_src, ps_dst);

    // launch 5: layer-1 aggregation  (ncu -s 5 captures THIS)
    agg_kernel<<<AGB, 256>>>(px0);
    // launch 6: layer-1 combine (relu)
    combine_kernel<64, true><<<CMB, 256, CMB64_SMEM>>>(pagg, px0, W1l, b1l, W1r, ph1);

    // launches 7-8: layer 2 -> d_out [N, 32]
    agg_kernel<<<AGB, 256>>>(ph1);
    combine_kernel<32, false><<<CMB, 256, CMB32_SMEM>>>(pagg, ph1, W2l, b2l, W2r, out);
}